// round 8
// baseline (speedup 1.0000x reference)
#include <cuda_runtime.h>
#include <cuda_bf16.h>
#include <cuda_fp8.h>
#include <cstdint>

// ---------------------------------------------------------------------------
// Problem constants
// ---------------------------------------------------------------------------
#define BATCH 4
#define DMODEL 768
#define NHEAD 12
#define HDIM 64
#define NLVL 3
#define NPT 4
#define LQ 4096
#define LIN 16464
#define NOFF 288
#define NATT 144
#define NCOMB 432
#define NCOMB_PAD 512

// GEMM tiling (K-tile is 128 BYTES: 64 bf16 or 128 fp8)
#define BM 128
#define BN 128
#define ROWB 144               // smem row stride bytes (128 + 16 pad)
#define TILEB (BM * ROWB)      // 18432 B per matrix-stage
#define GEMM_SMEM (4 * TILEB)  // 73728 B

#define WSCALE 64.0f           // fp8 weight pre-scale
#define WINV   (1.0f / 64.0f)

// ---------------------------------------------------------------------------
// Scratch (device globals; no runtime allocation allowed)
// ---------------------------------------------------------------------------
__device__ __nv_bfloat16 g_qln[(size_t)BATCH * LQ * DMODEL];
__device__ uint8_t       g_fln8[(size_t)BATCH * LIN * DMODEL];   // e4m3
__device__ uint8_t       g_val8[(size_t)BATCH * LIN * DMODEL];   // e4m3
__device__ float         g_off[(size_t)BATCH * LQ * NOFF];
__device__ float         g_aw [(size_t)BATCH * LQ * NATT];
__device__ uint8_t       g_sam8[(size_t)BATCH * LQ * DMODEL];    // e4m3
__device__ uint8_t       g_Wval8[DMODEL * DMODEL];               // [n][k] e4m3 (x64)
__device__ uint8_t       g_Wout8[DMODEL * DMODEL];               // [n][k] e4m3 (x64)
__device__ __nv_bfloat16 g_WcombT[NCOMB_PAD * DMODEL];           // [n][k] bf16

// ---------------------------------------------------------------------------
// helpers
// ---------------------------------------------------------------------------
__device__ __forceinline__ uint32_t smem_u32(const void* p) {
    uint32_t a;
    asm("{ .reg .u64 t; cvta.to.shared.u64 t, %1; cvt.u32.u64 %0, t; }" : "=r"(a) : "l"(p));
    return a;
}

#define CP_ASYNC16(sp, gp) \
    asm volatile("cp.async.cg.shared.global [%0], [%1], 16;" :: "r"(sp), "l"(gp) : "memory")
#define CP_COMMIT() asm volatile("cp.async.commit_group;" ::: "memory")
#define CP_WAIT1()  asm volatile("cp.async.wait_group 1;" ::: "memory")

#define LDSM_X4(r, addr)                                                      \
    asm volatile("ldmatrix.sync.aligned.m8n8.x4.shared.b16 {%0,%1,%2,%3}, [%4];" \
        : "=r"((r)[0]), "=r"((r)[1]), "=r"((r)[2]), "=r"((r)[3]) : "r"(addr))
#define LDSM_X2(r, addr)                                                      \
    asm volatile("ldmatrix.sync.aligned.m8n8.x2.shared.b16 {%0,%1}, [%2];"    \
        : "=r"((r)[0]), "=r"((r)[1]) : "r"(addr))

#define MMA_BF16(c, a, b)                                                     \
    asm volatile("mma.sync.aligned.m16n8k16.row.col.f32.bf16.bf16.f32 "       \
        "{%0,%1,%2,%3}, {%4,%5,%6,%7}, {%8,%9}, {%0,%1,%2,%3};"               \
        : "+f"((c)[0]), "+f"((c)[1]), "+f"((c)[2]), "+f"((c)[3])              \
        : "r"((a)[0]), "r"((a)[1]), "r"((a)[2]), "r"((a)[3]),                 \
          "r"((b)[0]), "r"((b)[1]))

#define MMA_FP8(c, a, b)                                                      \
    asm volatile("mma.sync.aligned.m16n8k32.row.col.f32.e4m3.e4m3.f32 "       \
        "{%0,%1,%2,%3}, {%4,%5,%6,%7}, {%8,%9}, {%0,%1,%2,%3};"               \
        : "+f"((c)[0]), "+f"((c)[1]), "+f"((c)[2]), "+f"((c)[3])              \
        : "r"((a)[0]), "r"((a)[1]), "r"((a)[2]), "r"((a)[3]),                 \
          "r"((b)[0]), "r"((b)[1]))

// pack (lo, hi) floats -> e4m3x2 (lo in low byte)
__device__ __forceinline__ uint16_t pack_e4m3x2(float lo, float hi) {
    uint16_t r;
    asm("cvt.rn.satfinite.e4m3x2.f32 %0, %1, %2;" : "=h"(r) : "f"(hi), "f"(lo));
    return r;
}
// e4m3x2 -> float2 (exact via f16x2)
__device__ __forceinline__ float2 unpack_e4m3x2(uint16_t v) {
    uint32_t h2;
    asm("cvt.rn.f16x2.e4m3x2 %0, %1;" : "=r"(h2) : "h"(v));
    __half2 hh = *reinterpret_cast<__half2*>(&h2);
    return __half22float2(hh);
}

// ---------------------------------------------------------------------------
// Tiled transposes
// ---------------------------------------------------------------------------
// fp32 [K,N] -> e4m3 [N,K] scaled by WSCALE
__global__ void __launch_bounds__(256) wtransF8_kernel(
    const float* __restrict__ W, uint8_t* __restrict__ Wt, int K, int N)
{
    __shared__ float t[32][33];
    const int kb = blockIdx.x * 32, nb = blockIdx.y * 32;
    const int tx = threadIdx.x & 31, ty = threadIdx.x >> 5;
#pragma unroll
    for (int i = 0; i < 32; i += 8) {
        int k = kb + ty + i, n = nb + tx;
        t[ty + i][tx] = (k < K && n < N) ? W[(size_t)k * N + n] : 0.f;
    }
    __syncthreads();
#pragma unroll
    for (int i = 0; i < 32; i += 8) {
        int n = nb + ty + i, k = kb + tx;
        if (n < N && k < K) {
            __nv_fp8_e4m3 q(t[tx][ty + i] * WSCALE);
            Wt[(size_t)n * K + k] = *reinterpret_cast<uint8_t*>(&q);
        }
    }
}

// combined off+attn transpose into padded [NCOMB_PAD, K] bf16
__global__ void __launch_bounds__(256) wtransC_kernel(
    const float* __restrict__ Woff, const float* __restrict__ Wattn,
    __nv_bfloat16* __restrict__ Wt)
{
    __shared__ float t[32][33];
    const int kb = blockIdx.x * 32, nb = blockIdx.y * 32;
    const int tx = threadIdx.x & 31, ty = threadIdx.x >> 5;
#pragma unroll
    for (int i = 0; i < 32; i += 8) {
        int k = kb + ty + i, n = nb + tx;
        float v = 0.f;
        if (k < DMODEL) {
            if (n < NOFF) v = Woff[(size_t)k * NOFF + n];
            else if (n < NCOMB) v = Wattn[(size_t)k * NATT + (n - NOFF)];
        }
        t[ty + i][tx] = v;
    }
    __syncthreads();
#pragma unroll
    for (int i = 0; i < 32; i += 8) {
        int n = nb + ty + i, k = kb + tx;
        if (n < NCOMB_PAD && k < DMODEL)
            Wt[(size_t)n * DMODEL + k] = __float2bfloat16(t[tx][ty + i]);
    }
}

// ---------------------------------------------------------------------------
// LayerNorm: one warp per row (768). OUTF8=0 -> bf16, OUTF8=1 -> e4m3
// ---------------------------------------------------------------------------
template <int OUTF8>
__global__ void __launch_bounds__(256) ln_kernel(
    const float* __restrict__ x, const float* __restrict__ g,
    const float* __restrict__ b, void* __restrict__ outv, int nrows)
{
    const int row = blockIdx.x * 8 + (threadIdx.x >> 5);
    const int lane = threadIdx.x & 31;
    if (row >= nrows) return;
    const float4* xr = reinterpret_cast<const float4*>(x + (size_t)row * DMODEL);
    float4 v[6];
    float s = 0.f, s2 = 0.f;
#pragma unroll
    for (int i = 0; i < 6; i++) {
        v[i] = xr[i * 32 + lane];
        s  += v[i].x + v[i].y + v[i].z + v[i].w;
        s2 += v[i].x * v[i].x + v[i].y * v[i].y + v[i].z * v[i].z + v[i].w * v[i].w;
    }
#pragma unroll
    for (int o = 16; o > 0; o >>= 1) {
        s  += __shfl_xor_sync(0xFFFFFFFFu, s,  o);
        s2 += __shfl_xor_sync(0xFFFFFFFFu, s2, o);
    }
    const float mean = s * (1.f / DMODEL);
    const float var  = s2 * (1.f / DMODEL) - mean * mean;
    const float rstd = rsqrtf(var + 1e-6f);
    const float4* gp = reinterpret_cast<const float4*>(g);
    const float4* bp = reinterpret_cast<const float4*>(b);
#pragma unroll
    for (int i = 0; i < 6; i++) {
        float4 gv = gp[i * 32 + lane];
        float4 bv = bp[i * 32 + lane];
        float r0 = (v[i].x - mean) * rstd * gv.x + bv.x;
        float r1 = (v[i].y - mean) * rstd * gv.y + bv.y;
        float r2 = (v[i].z - mean) * rstd * gv.z + bv.z;
        float r3 = (v[i].w - mean) * rstd * gv.w + bv.w;
        if (OUTF8) {
            uint32_t* o = reinterpret_cast<uint32_t*>((uint8_t*)outv + (size_t)row * DMODEL);
            uint32_t w = (uint32_t)pack_e4m3x2(r0, r1) |
                         ((uint32_t)pack_e4m3x2(r2, r3) << 16);
            o[i * 32 + lane] = w;
        } else {
            __nv_bfloat162 p0, p1;
            p0.x = __float2bfloat16(r0); p0.y = __float2bfloat16(r1);
            p1.x = __float2bfloat16(r2); p1.y = __float2bfloat16(r3);
            uint2 w;
            w.x = *reinterpret_cast<uint32_t*>(&p0);
            w.y = *reinterpret_cast<uint32_t*>(&p1);
            reinterpret_cast<uint2*>((__nv_bfloat16*)outv + (size_t)row * DMODEL)[i * 32 + lane] = w;
        }
    }
}

// ---------------------------------------------------------------------------
// mma.sync GEMM over A[M,768] @ Bt[N,768]^T (+bias).
// FP8=0: bf16 operands (k16 MMA).  FP8=1: e4m3 operands (k32 MMA), W scaled
// by WSCALE -> epilogue multiplies acc by WINV.
// K-tile = 128 bytes; cp.async double buffer; identical smem addressing.
// EPI 0: e4m3 C (value)     EPI 1: split off/attn float (bf16 path)
// EPI 2: float out = resid + gamma*(acc*scale+bias)  (fp8 path)
// ---------------------------------------------------------------------------
template <int EPI, int FP8>
__global__ void __launch_bounds__(256) gemm_mma_kernel(
    const void* __restrict__ Av, const void* __restrict__ Btv,
    int M, const float* __restrict__ bias0, const float* __restrict__ bias1,
    void* __restrict__ out0, void* __restrict__ out1,
    const float* __restrict__ resid, const float* __restrict__ gamma)
{
    extern __shared__ char smem[];
    const uint32_t sbase = smem_u32(smem);

    constexpr int KTILES = FP8 ? 6 : 12;            // 768 elems / (128 or 64)
    constexpr int AROWB  = FP8 ? DMODEL : DMODEL * 2;  // bytes per logical row

    const char* A  = (const char*)Av;
    const char* Bt = (const char*)Btv;

    const int tid  = threadIdx.x;
    const int wid  = tid >> 5;
    const int lane = tid & 31;
    const int wm   = wid >> 2;
    const int wn   = wid & 3;
    const int m0   = blockIdx.x * BM;
    const int n0   = blockIdx.y * BN;

    const uint32_t aOff[2] = {sbase, sbase + 2 * TILEB};
    const uint32_t bOff[2] = {sbase + TILEB, sbase + 3 * TILEB};

    float acc[4][4][4];
#pragma unroll
    for (int mi = 0; mi < 4; mi++)
#pragma unroll
        for (int ni = 0; ni < 4; ni++)
#pragma unroll
            for (int r = 0; r < 4; r++) acc[mi][ni][r] = 0.f;

    auto load_tile = [&](int kt, int s) {
        const size_t k0b = (size_t)kt * 128;
#pragma unroll
        for (int t = 0; t < 4; t++) {
            int c = t * 256 + tid;
            int row = c >> 3, col = c & 7;
            int ar = m0 + row; if (ar >= M) ar = M - 1;
            CP_ASYNC16(aOff[s] + row * ROWB + col * 16,
                       A + (size_t)ar * AROWB + k0b + col * 16);
            CP_ASYNC16(bOff[s] + row * ROWB + col * 16,
                       Bt + (size_t)(n0 + row) * AROWB + k0b + col * 16);
        }
    };

    const int alr = lane & 15;
    const int alc = lane >> 4;
    const int blr = lane & 7;
    const int blc = (lane >> 3) & 1;

    load_tile(0, 0);
    CP_COMMIT();

#pragma unroll 1
    for (int kt = 0; kt < KTILES; kt++) {
        const int s = kt & 1;
        if (kt + 1 < KTILES) load_tile(kt + 1, (kt + 1) & 1);
        CP_COMMIT();
        CP_WAIT1();
        __syncthreads();

        const uint32_t aBase = aOff[s] + (wm * 64 + alr) * ROWB + alc * 16;
        const uint32_t bBase = bOff[s] + (wn * 32 + blr) * ROWB + blc * 16;
#pragma unroll
        for (int ks = 0; ks < 4; ks++) {
            uint32_t af[4][4], bf[4][2];
#pragma unroll
            for (int mi = 0; mi < 4; mi++)
                LDSM_X4(af[mi], aBase + mi * 16 * ROWB + ks * 32);
#pragma unroll
            for (int ni = 0; ni < 4; ni++)
                LDSM_X2(bf[ni], bBase + ni * 8 * ROWB + ks * 32);
#pragma unroll
            for (int mi = 0; mi < 4; mi++)
#pragma unroll
                for (int ni = 0; ni < 4; ni++) {
                    if (FP8) { MMA_FP8(acc[mi][ni], af[mi], bf[ni]); }
                    else     { MMA_BF16(acc[mi][ni], af[mi], bf[ni]); }
                }
        }
        __syncthreads();
    }

    // ---------------- epilogue ----------------
    const float dsc = FP8 ? WINV : 1.0f;
    const int groupID = lane >> 2, tig = lane & 3;
#pragma unroll
    for (int mi = 0; mi < 4; mi++) {
        const int r0 = m0 + wm * 64 + mi * 16 + groupID;
        const int r1 = r0 + 8;
#pragma unroll
        for (int ni = 0; ni < 4; ni++) {
            const int cb = n0 + wn * 32 + ni * 8 + tig * 2;
            const float* a4 = acc[mi][ni];
            if (EPI == 0) {
                uint8_t* o = (uint8_t*)out0;
                float b0v = bias0[cb], b1v = bias0[cb + 1];
                if (r0 < M)
                    *reinterpret_cast<uint16_t*>(o + (size_t)r0 * DMODEL + cb) =
                        pack_e4m3x2(a4[0] * dsc + b0v, a4[1] * dsc + b1v);
                if (r1 < M)
                    *reinterpret_cast<uint16_t*>(o + (size_t)r1 * DMODEL + cb) =
                        pack_e4m3x2(a4[2] * dsc + b0v, a4[3] * dsc + b1v);
            } else if (EPI == 1) {
                float* o0 = (float*)out0;
                float* o1 = (float*)out1;
#pragma unroll
                for (int e = 0; e < 2; e++) {
                    int n = cb + e;
                    float v0 = a4[e] * dsc, v1 = a4[2 + e] * dsc;
                    if (n < NOFF) {
                        o0[(size_t)r0 * NOFF + n] = v0 + bias0[n];
                        o0[(size_t)r1 * NOFF + n] = v1 + bias0[n];
                    } else if (n < NCOMB) {
                        o1[(size_t)r0 * NATT + (n - NOFF)] = v0 + bias1[n - NOFF];
                        o1[(size_t)r1 * NATT + (n - NOFF)] = v1 + bias1[n - NOFF];
                    }
                }
            } else {
                float* o = (float*)out0;
#pragma unroll
                for (int e = 0; e < 2; e++) {
                    int n = cb + e;
                    o[(size_t)r0 * DMODEL + n] = resid[(size_t)r0 * DMODEL + n] +
                                                 gamma[n] * (a4[e] * dsc + bias0[n]);
                    o[(size_t)r1 * DMODEL + n] = resid[(size_t)r1 * DMODEL + n] +
                                                 gamma[n] * (a4[2 + e] * dsc + bias0[n]);
                }
            }
        }
    }
}

// ---------------------------------------------------------------------------
// Deformable sampling + fused softmax: one warp per (b, q, h).
// val in e4m3; sam out e4m3.
// ---------------------------------------------------------------------------
__global__ void __launch_bounds__(256) sample_kernel(
    const float* __restrict__ off, const float* __restrict__ aw,
    const uint8_t* __restrict__ val, uint8_t* __restrict__ sam)
{
    constexpr int lvl_h[3] = {112, 56, 28};
    constexpr int lvl_w[3] = {112, 56, 28};
    constexpr int lvl_s[3] = {0, 12544, 15680};

    int warp = (blockIdx.x * blockDim.x + threadIdx.x) >> 5;
    int lane = threadIdx.x & 31;
    if (warp >= BATCH * LQ * NHEAD) return;
    int h  = warp % NHEAD;
    int bq = warp / NHEAD;
    int q  = bq % LQ;
    int b  = bq / LQ;

    float rx = ((q & 63) + 0.5f) * (1.f / 64.f);
    float ry = ((q >> 6) + 0.5f) * (1.f / 64.f);

    const float* offp = off + (size_t)warp * (NLVL * NPT * 2);
    const float* awp  = aw  + (size_t)warp * (NLVL * NPT);

    float lg[12];
    float mx = -1e30f;
#pragma unroll
    for (int j = 0; j < 12; j++) { lg[j] = awp[j]; mx = fmaxf(mx, lg[j]); }
    float ssum = 0.f;
#pragma unroll
    for (int j = 0; j < 12; j++) { lg[j] = __expf(lg[j] - mx); ssum += lg[j]; }
    const float sinv = 1.f / ssum;

    float acc0 = 0.f, acc1 = 0.f;

#pragma unroll
    for (int l = 0; l < NLVL; l++) {
        const int h_ = lvl_h[l], w_ = lvl_w[l], st = lvl_s[l];
        const float invw = 1.f / (float)w_, invh = 1.f / (float)h_;
#pragma unroll
        for (int p = 0; p < NPT; p++) {
            float ox = offp[(l * NPT + p) * 2];
            float oy = offp[(l * NPT + p) * 2 + 1];
            float a  = lg[l * NPT + p] * sinv;
            float x = (rx + ox * invw) * (float)w_ - 0.5f;
            float y = (ry + oy * invh) * (float)h_ - 0.5f;
            float x0f = floorf(x), y0f = floorf(y);
            float wx = x - x0f, wy = y - y0f;
            int x0 = (int)x0f, y0 = (int)y0f;
            float w00 = (1.f - wx) * (1.f - wy) * a;
            float w01 = wx * (1.f - wy) * a;
            float w10 = (1.f - wx) * wy * a;
            float w11 = wx * wy * a;

            const int xs[4] = {x0, x0 + 1, x0, x0 + 1};
            const int ys[4] = {y0, y0, y0 + 1, y0 + 1};
            const float ws[4] = {w00, w01, w10, w11};
#pragma unroll
            for (int c = 0; c < 4; c++) {
                int xi = xs[c], yi = ys[c];
                if (xi >= 0 && xi < w_ && yi >= 0 && yi < h_) {
                    size_t base = (((size_t)b * LIN + st + (size_t)yi * w_ + xi) * NHEAD + h)
                                  * HDIM + lane * 2;
                    uint16_t v2 = *reinterpret_cast<const uint16_t*>(val + base);
                    float2 f = unpack_e4m3x2(v2);
                    acc0 += ws[c] * f.x;
                    acc1 += ws[c] * f.y;
                }
            }
        }
    }

    size_t so = (size_t)(b * LQ + q) * DMODEL + h * HDIM + lane * 2;
    *reinterpret_cast<uint16_t*>(sam + so) = pack_e4m3x2(acc0, acc1);
}

// ---------------------------------------------------------------------------
// Launch
// ---------------------------------------------------------------------------
extern "C" void kernel_launch(void* const* d_in, const int* in_sizes, int n_in,
                              void* d_out, int out_size)
{
    const float* query  = (const float*)d_in[0];
    const float* feat   = (const float*)d_in[1];
    const float* ln_q_g = (const float*)d_in[2];
    const float* ln_q_b = (const float*)d_in[3];
    const float* ln_f_g = (const float*)d_in[4];
    const float* ln_f_b = (const float*)d_in[5];
    const float* W_off  = (const float*)d_in[6];
    const float* b_off  = (const float*)d_in[7];
    const float* W_attn = (const float*)d_in[8];
    const float* b_attn = (const float*)d_in[9];
    const float* W_val  = (const float*)d_in[10];
    const float* b_val  = (const float*)d_in[11];
    const float* W_out  = (const float*)d_in[12];
    const float* b_out  = (const float*)d_in[13];
    const float* gamma  = (const float*)d_in[14];
    float* out = (float*)d_out;

    __nv_bfloat16 *p_qln, *p_WcombT;
    uint8_t *p_fln8, *p_val8, *p_sam8, *p_Wval8, *p_Wout8;
    float *p_off, *p_aw;
    cudaGetSymbolAddress((void**)&p_qln,   g_qln);
    cudaGetSymbolAddress((void**)&p_fln8,  g_fln8);
    cudaGetSymbolAddress((void**)&p_val8,  g_val8);
    cudaGetSymbolAddress((void**)&p_sam8,  g_sam8);
    cudaGetSymbolAddress((void**)&p_Wval8, g_Wval8);
    cudaGetSymbolAddress((void**)&p_Wout8, g_Wout8);
    cudaGetSymbolAddress((void**)&p_WcombT,g_WcombT);
    cudaGetSymbolAddress((void**)&p_off,   g_off);
    cudaGetSymbolAddress((void**)&p_aw,    g_aw);

    cudaFuncSetAttribute(gemm_mma_kernel<0,1>, cudaFuncAttributeMaxDynamicSharedMemorySize, GEMM_SMEM);
    cudaFuncSetAttribute(gemm_mma_kernel<1,0>, cudaFuncAttributeMaxDynamicSharedMemorySize, GEMM_SMEM);
    cudaFuncSetAttribute(gemm_mma_kernel<2,1>, cudaFuncAttributeMaxDynamicSharedMemorySize, GEMM_SMEM);

    const int Mq = BATCH * LQ;    // 16384
    const int Mf = BATCH * LIN;   // 65856

    // 1. weight prep
    wtransF8_kernel<<<dim3(DMODEL / 32, DMODEL / 32), 256>>>(W_val, p_Wval8, DMODEL, DMODEL);
    wtransF8_kernel<<<dim3(DMODEL / 32, DMODEL / 32), 256>>>(W_out, p_Wout8, DMODEL, DMODEL);
    wtransC_kernel<<<dim3(DMODEL / 32, NCOMB_PAD / 32), 256>>>(W_off, W_attn, p_WcombT);

    // 2. LayerNorms (feat -> e4m3, query -> bf16)
    ln_kernel<1><<<(Mf + 7) / 8, 256>>>(feat, ln_f_g, ln_f_b, p_fln8, Mf);
    ln_kernel<0><<<(Mq + 7) / 8, 256>>>(query, ln_q_g, ln_q_b, p_qln, Mq);

    // 3. value = ln(feat) @ W_val + b_val   (fp8 x fp8 -> e4m3 out)
    gemm_mma_kernel<0,1><<<dim3((Mf + BM - 1) / BM, DMODEL / BN), 256, GEMM_SMEM>>>(
        p_fln8, p_Wval8, Mf, b_val, nullptr, p_val8, nullptr, nullptr, nullptr);

    // 4+5. fused offsets+attn logits (bf16, split epilogue)
    gemm_mma_kernel<1,0><<<dim3(Mq / BM, NCOMB_PAD / BN), 256, GEMM_SMEM>>>(
        p_qln, p_WcombT, Mq, b_off, b_attn, p_off, p_aw, nullptr, nullptr);

    // 6+7. deformable sampling with fused softmax -> g_sam8 (e4m3)
    sample_kernel<<<(Mq * NHEAD) / 8, 256>>>(p_off, p_aw, p_val8, p_sam8);

    // 8. out = query + gamma * (g_sam @ W_out + b_out)  (fp8 x fp8)
    gemm_mma_kernel<2,1><<<dim3(Mq / BM, DMODEL / BN), 256, GEMM_SMEM>>>(
        p_sam8, p_Wout8, Mq, b_out, nullptr, out, nullptr, query, gamma);
}